// round 1
// baseline (speedup 1.0000x reference)
#include <cuda_runtime.h>
#include <math.h>

#define SLEN   2048
#define DMODEL 1024
#define NH     16
#define HDIM   64
#define NLAYER 4
#define FFND   4096
#define OUTD   128
#define IND    64

// ---------------- scratch (module-load allocated, no cudaMalloc) -------------
__device__ float g_h [SLEN * DMODEL];
__device__ float g_hn[SLEN * DMODEL];
__device__ float g_q [SLEN * DMODEL];
__device__ float g_k [SLEN * DMODEL];
__device__ float g_v [SLEN * DMODEL];
__device__ float g_o [SLEN * DMODEL];
__device__ float g_f1[SLEN * FFND];
__device__ float g_f3[SLEN * FFND];

// ---------------- SGEMM: C[M,N] = A[M,K] @ B[K,N] (+bias) (+res) -------------
// BM=128, BN=128, BK=8, 256 threads, 8x8 per thread.
// Requires: M%128==0, N%128==0, K%8==0 (true for every GEMM in this model).
template <bool BIAS, bool RES>
__global__ void sgemm_kernel(const float* __restrict__ A,
                             const float* __restrict__ B,
                             const float* __restrict__ bias,
                             const float* __restrict__ res,
                             float* __restrict__ C,
                             int M, int N, int K)
{
    __shared__ float As[8][128];
    __shared__ float Bs[8][128];

    const int tid = threadIdx.x;           // 0..255
    const int tx  = tid & 15;              // 0..15  (N dir)
    const int ty  = tid >> 4;              // 0..15  (M dir)

    const float* Ab = A + (size_t)blockIdx.y * 128 * K;
    const float* Bb = B + (size_t)blockIdx.x * 128;

    const int arow = tid >> 1;             // 0..127
    const int acol = (tid & 1) * 4;        // 0 or 4
    const int brow = tid >> 5;             // 0..7
    const int bcol = (tid & 31) * 4;       // 0..124

    float acc[8][8];
    #pragma unroll
    for (int i = 0; i < 8; i++)
        #pragma unroll
        for (int j = 0; j < 8; j++) acc[i][j] = 0.f;

    for (int k0 = 0; k0 < K; k0 += 8) {
        float4 av = *(const float4*)(Ab + (size_t)arow * K + k0 + acol);
        As[acol + 0][arow] = av.x;
        As[acol + 1][arow] = av.y;
        As[acol + 2][arow] = av.z;
        As[acol + 3][arow] = av.w;
        float4 bv = *(const float4*)(Bb + (size_t)(k0 + brow) * N + bcol);
        *(float4*)&Bs[brow][bcol] = bv;
        __syncthreads();

        #pragma unroll
        for (int kk = 0; kk < 8; kk++) {
            float a[8], b[8];
            #pragma unroll
            for (int i = 0; i < 8; i++) a[i] = As[kk][ty * 8 + i];
            #pragma unroll
            for (int j = 0; j < 8; j++) b[j] = Bs[kk][tx * 8 + j];
            #pragma unroll
            for (int i = 0; i < 8; i++)
                #pragma unroll
                for (int j = 0; j < 8; j++) acc[i][j] += a[i] * b[j];
        }
        __syncthreads();
    }

    const int rowb = blockIdx.y * 128 + ty * 8;
    const int colb = blockIdx.x * 128 + tx * 8;
    #pragma unroll
    for (int i = 0; i < 8; i++) {
        size_t off = (size_t)(rowb + i) * N + colb;
        #pragma unroll
        for (int j = 0; j < 8; j++) {
            float v = acc[i][j];
            if (BIAS) v += bias[colb + j];
            if (RES)  v += res[off + j];
            C[off + j] = v;
        }
    }
}

// ---------------- RMSNorm (one block per row) --------------------------------
__global__ void rmsnorm_kernel(const float* __restrict__ x,
                               const float* __restrict__ w,
                               float* __restrict__ out)
{
    const int row = blockIdx.x;
    const float* xr = x + (size_t)row * DMODEL;
    float s = 0.f;
    for (int i = threadIdx.x; i < DMODEL; i += 256) { float v = xr[i]; s += v * v; }
    #pragma unroll
    for (int off = 16; off; off >>= 1) s += __shfl_down_sync(0xffffffffu, s, off);
    __shared__ float red[8];
    const int warp = threadIdx.x >> 5, lane = threadIdx.x & 31;
    if (lane == 0) red[warp] = s;
    __syncthreads();
    if (warp == 0) {
        float t = (lane < 8) ? red[lane] : 0.f;
        #pragma unroll
        for (int off = 4; off; off >>= 1) t += __shfl_down_sync(0xffu, t, off);
        if (lane == 0) red[0] = t;
    }
    __syncthreads();
    const float inv = rsqrtf(red[0] * (1.0f / DMODEL) + 1e-5f);
    for (int i = threadIdx.x; i < DMODEL; i += 256)
        out[(size_t)row * DMODEL + i] = xr[i] * inv * w[i];
}

// ---------------- RoPE (in place on q and k) ---------------------------------
// double-precision angle/sincos: immune to --use_fast_math range reduction.
__global__ void rope_kernel(float* __restrict__ q, float* __restrict__ k,
                            const int* __restrict__ tok_id)
{
    const int idx = blockIdx.x * blockDim.x + threadIdx.x;
    if (idx >= SLEN * NH * 32) return;
    const int i = idx & 31;
    const int h = (idx >> 5) & 15;
    const int s = idx >> 9;
    const double inv = pow(10000.0, -(double)i / 32.0);
    const double ang = (double)tok_id[s] * inv;
    double sd, cd;
    sincos(ang, &sd, &cd);
    const float c = (float)cd, sn = (float)sd;
    const size_t base = (size_t)s * DMODEL + h * HDIM;
    float x1 = q[base + i], x2 = q[base + 32 + i];
    q[base + i]      = x1 * c - x2 * sn;
    q[base + 32 + i] = x1 * sn + x2 * c;
    float y1 = k[base + i], y2 = k[base + 32 + i];
    k[base + i]      = y1 * c - y2 * sn;
    k[base + 32 + i] = y1 * sn + y2 * c;
}

// ---------------- Local masked attention -------------------------------------
// Mask support is contained in [s-127, s+127] (same 256-doc AND |dtok|<128).
// One block per (query, head): 128 threads, <=255 keys.
__global__ void attn_kernel(const float* __restrict__ q,
                            const float* __restrict__ k,
                            const float* __restrict__ v,
                            const int* __restrict__ doc_id,
                            const int* __restrict__ tok_id,
                            float* __restrict__ o)
{
    const int s = blockIdx.x;
    const int h = blockIdx.y;
    const int tid = threadIdx.x;
    const int warp = tid >> 5, lane = tid & 31;

    __shared__ float qs[HDIM];
    __shared__ float sc[256];
    __shared__ float red[4];
    __shared__ float oacc[HDIM];

    if (tid < HDIM) qs[tid] = q[(size_t)s * DMODEL + h * HDIM + tid];
    __syncthreads();

    int kstart = s - 127; if (kstart < 0) kstart = 0;
    int kend   = s + 127; if (kend > SLEN - 1) kend = SLEN - 1;
    const int nk = kend - kstart + 1;
    const int myDoc = doc_id[s];
    const int myTok = tok_id[s];

    for (int j = warp; j < nk; j += 4) {
        const int kk = kstart + j;
        const size_t kb = (size_t)kk * DMODEL + h * HDIM;
        float p = qs[lane] * k[kb + lane] + qs[lane + 32] * k[kb + lane + 32];
        #pragma unroll
        for (int off = 16; off; off >>= 1) p += __shfl_down_sync(0xffffffffu, p, off);
        if (lane == 0) {
            const bool ok = (doc_id[kk] == myDoc) && (abs(tok_id[kk] - myTok) < 128);
            sc[j] = ok ? p * 0.125f : -1e30f;   // scale = 1/sqrt(64)
        }
    }
    __syncthreads();

    // max
    float m = -1e30f;
    for (int j = tid; j < nk; j += 128) m = fmaxf(m, sc[j]);
    #pragma unroll
    for (int off = 16; off; off >>= 1) m = fmaxf(m, __shfl_down_sync(0xffffffffu, m, off));
    if (lane == 0) red[warp] = m;
    __syncthreads();
    m = fmaxf(fmaxf(red[0], red[1]), fmaxf(red[2], red[3]));
    __syncthreads();

    // exp + sum
    float sum = 0.f;
    for (int j = tid; j < nk; j += 128) {
        const float e = expf(sc[j] - m);
        sc[j] = e;
        sum += e;
    }
    #pragma unroll
    for (int off = 16; off; off >>= 1) sum += __shfl_down_sync(0xffffffffu, sum, off);
    if (lane == 0) red[warp] = sum;
    __syncthreads();
    sum = red[0] + red[1] + red[2] + red[3];
    const float inv = 1.0f / sum;
    __syncthreads();

    // output: 2 halves of threads split keys, then combine
    const int d = tid & 63;
    const int half = tid >> 6;
    float acc = 0.f;
    for (int j = half; j < nk; j += 2)
        acc += sc[j] * v[(size_t)(kstart + j) * DMODEL + h * HDIM + d];
    if (half == 1) oacc[d] = acc;
    __syncthreads();
    if (half == 0)
        o[(size_t)s * DMODEL + h * HDIM + d] = (acc + oacc[d]) * inv;
}

// ---------------- SiLU gate: f1 = silu(f1) * f3 ------------------------------
__global__ void silu_kernel(float* __restrict__ f1, const float* __restrict__ f3)
{
    const int idx = blockIdx.x * blockDim.x + threadIdx.x;
    const float a = f1[idx];
    f1[idx] = (a / (1.0f + expf(-a))) * f3[idx];
}

// ---------------- launch -----------------------------------------------------
extern "C" void kernel_launch(void* const* d_in, const int* in_sizes, int n_in,
                              void* d_out, int out_size)
{
    const float* x           = (const float*)d_in[0];
    const float* emb_w       = (const float*)d_in[1];
    const float* emb_b       = (const float*)d_in[2];
    const float* wq          = (const float*)d_in[3];
    const float* wk          = (const float*)d_in[4];
    const float* wv          = (const float*)d_in[5];
    const float* wo          = (const float*)d_in[6];
    const float* attn_norm_w = (const float*)d_in[7];
    const float* ffn_norm_w  = (const float*)d_in[8];
    const float* w1          = (const float*)d_in[9];
    const float* w2          = (const float*)d_in[10];
    const float* w3          = (const float*)d_in[11];
    const float* out_norm_w  = (const float*)d_in[12];
    const float* out_w       = (const float*)d_in[13];
    const int*   doc_id      = (const int*)d_in[14];
    const int*   tok_id      = (const int*)d_in[15];
    float* out = (float*)d_out;

    float *h, *hn, *q, *k, *v, *o, *f1, *f3;
    cudaGetSymbolAddress((void**)&h,  g_h);
    cudaGetSymbolAddress((void**)&hn, g_hn);
    cudaGetSymbolAddress((void**)&q,  g_q);
    cudaGetSymbolAddress((void**)&k,  g_k);
    cudaGetSymbolAddress((void**)&v,  g_v);
    cudaGetSymbolAddress((void**)&o,  g_o);
    cudaGetSymbolAddress((void**)&f1, g_f1);
    cudaGetSymbolAddress((void**)&f3, g_f3);

    const dim3 gD (DMODEL / 128, SLEN / 128);   // (8,16)
    const dim3 gF (FFND   / 128, SLEN / 128);   // (32,16)
    const dim3 gO (OUTD   / 128, SLEN / 128);   // (1,16)

    // embedding: h = x @ emb_w + emb_b
    sgemm_kernel<true, false><<<gD, 256>>>(x, emb_w, emb_b, nullptr, h,
                                           SLEN, DMODEL, IND);

    for (int l = 0; l < NLAYER; l++) {
        const size_t wqo  = (size_t)l * DMODEL * (NH * HDIM);
        const size_t wffn = (size_t)l * DMODEL * FFND;

        rmsnorm_kernel<<<SLEN, 256>>>(h, attn_norm_w + (size_t)l * DMODEL, hn);

        sgemm_kernel<false, false><<<gD, 256>>>(hn, wq + wqo, nullptr, nullptr, q,
                                                SLEN, DMODEL, DMODEL);
        sgemm_kernel<false, false><<<gD, 256>>>(hn, wk + wqo, nullptr, nullptr, k,
                                                SLEN, DMODEL, DMODEL);
        sgemm_kernel<false, false><<<gD, 256>>>(hn, wv + wqo, nullptr, nullptr, v,
                                                SLEN, DMODEL, DMODEL);

        rope_kernel<<<(SLEN * NH * 32 + 255) / 256, 256>>>(q, k, tok_id);

        attn_kernel<<<dim3(SLEN, NH), 128>>>(q, k, v, doc_id, tok_id, o);

        // h = h + o @ wo
        sgemm_kernel<false, true><<<gD, 256>>>(o, wo + wqo, nullptr, h, h,
                                               SLEN, DMODEL, DMODEL);

        rmsnorm_kernel<<<SLEN, 256>>>(h, ffn_norm_w + (size_t)l * DMODEL, hn);

        sgemm_kernel<false, false><<<gF, 256>>>(hn, w1 + wffn, nullptr, nullptr, f1,
                                                SLEN, FFND, DMODEL);
        sgemm_kernel<false, false><<<gF, 256>>>(hn, w3 + wffn, nullptr, nullptr, f3,
                                                SLEN, FFND, DMODEL);

        silu_kernel<<<(SLEN * FFND) / 256, 256>>>(f1, f3);

        // h = h + f1 @ w2
        sgemm_kernel<false, true><<<gD, 256>>>(f1, w2 + (size_t)l * FFND * DMODEL,
                                               nullptr, h, h, SLEN, DMODEL, FFND);
    }

    rmsnorm_kernel<<<SLEN, 256>>>(h, out_norm_w, hn);
    sgemm_kernel<false, false><<<gO, 256>>>(hn, out_w, nullptr, nullptr, out,
                                            SLEN, OUTD, DMODEL);
}

// round 3
// speedup vs baseline: 1.9436x; 1.9436x over previous
#include <cuda_runtime.h>
#include <cuda_bf16.h>
#include <math.h>
#include <stdint.h>

#define SLEN   2048
#define DMODEL 1024
#define NH     16
#define HDIM   64
#define NLAYER 4
#define FFND   4096
#define OUTD   128
#define IND    64

// ======================= helpers =============================================
__device__ __forceinline__ uint32_t smem_u32(const void* p) {
    uint32_t a;
    asm("{ .reg .u64 t; cvta.to.shared.u64 t, %1; cvt.u32.u64 %0, t; }"
        : "=r"(a) : "l"(p));
    return a;
}
__device__ __forceinline__ uint64_t gmem_u64(const void* p) {
    uint64_t a;
    asm("cvta.to.global.u64 %0, %1;" : "=l"(a) : "l"(p));
    return a;
}
__device__ __forceinline__ void cp_async16(uint32_t dst, uint64_t src) {
    asm volatile("cp.async.cg.shared.global [%0], [%1], 16;" :: "r"(dst), "l"(src));
}
__device__ __forceinline__ void cp_commit() {
    asm volatile("cp.async.commit_group;" ::: "memory");
}
template <int NN> __device__ __forceinline__ void cp_wait() {
    asm volatile("cp.async.wait_group %0;" :: "n"(NN) : "memory");
}
__device__ __forceinline__ void ldm_x4(uint32_t* r, uint32_t addr) {
    asm volatile("ldmatrix.sync.aligned.m8n8.x4.shared.b16 {%0,%1,%2,%3}, [%4];"
                 : "=r"(r[0]), "=r"(r[1]), "=r"(r[2]), "=r"(r[3]) : "r"(addr));
}
__device__ __forceinline__ void ldm_x2(uint32_t* r, uint32_t addr) {
    asm volatile("ldmatrix.sync.aligned.m8n8.x2.shared.b16 {%0,%1}, [%2];"
                 : "=r"(r[0]), "=r"(r[1]) : "r"(addr));
}
__device__ __forceinline__ void mma_bf16(float* c, const uint32_t* a, const uint32_t* b) {
    asm volatile(
        "mma.sync.aligned.m16n8k16.row.col.f32.bf16.bf16.f32 "
        "{%0,%1,%2,%3}, {%4,%5,%6,%7}, {%8,%9}, {%0,%1,%2,%3};"
        : "+f"(c[0]), "+f"(c[1]), "+f"(c[2]), "+f"(c[3])
        : "r"(a[0]), "r"(a[1]), "r"(a[2]), "r"(a[3]), "r"(b[0]), "r"(b[1]));
}

// ======================= scratch =============================================
#define MEG 1048576u
#define WTOT (65536u + 4u*16u*MEG + 131072u)
__device__ __nv_bfloat16 g_whi[WTOT];
__device__ __nv_bfloat16 g_wlo[WTOT];
__device__ __nv_bfloat16 g_ahi[SLEN * FFND];
__device__ __nv_bfloat16 g_alo[SLEN * FFND];

__device__ float g_h [SLEN * DMODEL];
__device__ float g_hn[SLEN * DMODEL];
__device__ float g_q [SLEN * DMODEL];
__device__ float g_k [SLEN * DMODEL];
__device__ float g_v [SLEN * DMODEL];
__device__ float g_o [SLEN * DMODEL];
__device__ float g_f1[SLEN * FFND];
__device__ float g_f3[SLEN * FFND];

// ============ weight transpose + hi/lo bf16 split:  W[K,N] -> T[N,K] =========
__global__ void wconv_kernel(const float* __restrict__ W,
                             __nv_bfloat16* __restrict__ Thi,
                             __nv_bfloat16* __restrict__ Tlo, int K, int N)
{
    __shared__ float t[32][33];
    const int n0 = blockIdx.x * 32, k0 = blockIdx.y * 32;
    const int tx = threadIdx.x, ty = threadIdx.y;  // 32 x 8
    #pragma unroll
    for (int j = 0; j < 32; j += 8)
        t[ty + j][tx] = W[(size_t)(k0 + ty + j) * N + n0 + tx];
    __syncthreads();
    #pragma unroll
    for (int j = 0; j < 32; j += 8) {
        float v = t[tx][ty + j];
        __nv_bfloat16 hi = __float2bfloat16(v);
        float lo = v - __bfloat162float(hi);
        size_t o = (size_t)(n0 + ty + j) * K + k0 + tx;
        Thi[o] = hi;
        Tlo[o] = __float2bfloat16(lo);
    }
}

// ============ activation hi/lo bf16 split ====================================
__global__ void aconv_kernel(const float* __restrict__ A,
                             __nv_bfloat16* __restrict__ hi,
                             __nv_bfloat16* __restrict__ lo, int n4)
{
    const int i = blockIdx.x * blockDim.x + threadIdx.x;
    if (i >= n4) return;
    float4 v = ((const float4*)A)[i];
    __nv_bfloat16 h0 = __float2bfloat16(v.x), h1 = __float2bfloat16(v.y);
    __nv_bfloat16 h2 = __float2bfloat16(v.z), h3 = __float2bfloat16(v.w);
    __nv_bfloat16 l0 = __float2bfloat16(v.x - __bfloat162float(h0));
    __nv_bfloat16 l1 = __float2bfloat16(v.y - __bfloat162float(h1));
    __nv_bfloat16 l2 = __float2bfloat16(v.z - __bfloat162float(h2));
    __nv_bfloat16 l3 = __float2bfloat16(v.w - __bfloat162float(h3));
    ((__nv_bfloat162*)hi)[2 * i]     = __halves2bfloat162(h0, h1);
    ((__nv_bfloat162*)hi)[2 * i + 1] = __halves2bfloat162(h2, h3);
    ((__nv_bfloat162*)lo)[2 * i]     = __halves2bfloat162(l0, l1);
    ((__nv_bfloat162*)lo)[2 * i + 1] = __halves2bfloat162(l2, l3);
}

// ============ HMMA GEMM:  C[M,N] = A[M,K] * Bt[N,K]^T  (+bias)(+res) =========
// CTA 128x128, 8 warps (warp tile 64x32), K-chunk 32, cp.async double buffer.
// Hi/lo compensated: C = Ah*Bh + Ah*Bl + Al*Bh (fp32 accum).
// Requires M%128==0, N%128==0, K%32==0.
#define TILE_B   10240          // 128 rows * 80 bytes
#define STAGE_B  (4 * TILE_B)   // Ahi, Alo, Bhi, Blo
#define HG_SMEM  (2 * STAGE_B)  // 81920

__global__ void __launch_bounds__(256)
hgemm_kernel(const __nv_bfloat16* __restrict__ Ahi,
             const __nv_bfloat16* __restrict__ Alo,
             const __nv_bfloat16* __restrict__ Bhi,
             const __nv_bfloat16* __restrict__ Blo,
             const float* __restrict__ bias,
             const float* __restrict__ res,
             float* __restrict__ C, int M, int N, int K)
{
    extern __shared__ char sm[];
    const uint32_t smb = smem_u32(sm);

    const int tid  = threadIdx.x;
    const int wid  = tid >> 5, lane = tid & 31;
    const int wm   = wid >> 2;          // 0..1  (M dir, 64 rows)
    const int wn   = wid & 3;           // 0..3  (N dir, 32 cols)
    const int m0 = blockIdx.y * 128, n0 = blockIdx.x * 128;

    const uint64_t srcA[2] = { gmem_u64(Ahi + (size_t)m0 * K),
                               gmem_u64(Alo + (size_t)m0 * K) };
    const uint64_t srcB[2] = { gmem_u64(Bhi + (size_t)n0 * K),
                               gmem_u64(Blo + (size_t)n0 * K) };

    const int nc = K >> 5;

    // loader mapping: 2 iters x 256 threads cover 512 x 16B per tile
    const int lrow = tid >> 2;            // 0..63 (+64 second iter)
    const int lgrp = tid & 3;             // 16B group within 64B row-chunk

    auto load_chunk = [&](int c, int s) {
        const uint32_t stage = smb + s * STAGE_B;
        #pragma unroll
        for (int t = 0; t < 4; t++) {
            const uint64_t src = (t < 2 ? srcA[t] : srcB[t - 2]) +
                                 (uint64_t)c * 64;  // c*32 elems * 2B
            const uint32_t dst = stage + t * TILE_B;
            #pragma unroll
            for (int i = 0; i < 2; i++) {
                const int row = lrow + i * 64;
                cp_async16(dst + row * 80 + lgrp * 16,
                           src + (uint64_t)row * K * 2 + lgrp * 16);
            }
        }
        cp_commit();
    };

    float acc[4][4][4];
    #pragma unroll
    for (int a = 0; a < 4; a++)
        #pragma unroll
        for (int b = 0; b < 4; b++)
            #pragma unroll
            for (int r = 0; r < 4; r++) acc[a][b][r] = 0.f;

    load_chunk(0, 0);

    for (int c = 0; c < nc; c++) {
        if (c + 1 < nc) { load_chunk(c + 1, (c + 1) & 1); cp_wait<1>(); }
        else            { cp_wait<0>(); }
        __syncthreads();

        const uint32_t stage = smb + (c & 1) * STAGE_B;
        const uint32_t sAh = stage, sAl = stage + TILE_B;
        const uint32_t sBh = stage + 2 * TILE_B, sBl = stage + 3 * TILE_B;

        #pragma unroll
        for (int ks = 0; ks < 2; ks++) {
            const uint32_t cb = ks * 32 + ((lane >> 4) * 16);
            uint32_t ah[4][4], al[4][4];
            #pragma unroll
            for (int mt = 0; mt < 4; mt++) {
                const uint32_t ro = (wm * 64 + mt * 16 + (lane & 15)) * 80 + cb;
                ldm_x4(ah[mt], sAh + ro);
                ldm_x4(al[mt], sAl + ro);
            }
            #pragma unroll
            for (int nt = 0; nt < 4; nt++) {
                const uint32_t ro = (wn * 32 + nt * 8 + (lane & 7)) * 80 +
                                    ks * 32 + (((lane >> 3) & 1) * 16);
                uint32_t bh[2], bl[2];
                ldm_x2(bh, sBh + ro);
                ldm_x2(bl, sBl + ro);
                #pragma unroll
                for (int mt = 0; mt < 4; mt++) {
                    mma_bf16(acc[mt][nt], ah[mt], bh);
                    mma_bf16(acc[mt][nt], ah[mt], bl);
                    mma_bf16(acc[mt][nt], al[mt], bh);
                }
            }
        }
        __syncthreads();
    }

    // epilogue
    #pragma unroll
    for (int mt = 0; mt < 4; mt++) {
        #pragma unroll
        for (int nt = 0; nt < 4; nt++) {
            const int col = n0 + wn * 32 + nt * 8 + (lane & 3) * 2;
            float bv0 = 0.f, bv1 = 0.f;
            if (bias) { bv0 = bias[col]; bv1 = bias[col + 1]; }
            #pragma unroll
            for (int hh = 0; hh < 2; hh++) {
                const int row = m0 + wm * 64 + mt * 16 + (lane >> 2) + hh * 8;
                float v0 = acc[mt][nt][hh * 2]     + bv0;
                float v1 = acc[mt][nt][hh * 2 + 1] + bv1;
                const size_t off = (size_t)row * N + col;
                if (res) { v0 += res[off]; v1 += res[off + 1]; }
                C[off]     = v0;
                C[off + 1] = v1;
            }
        }
    }
}

// ======================= RMSNorm =============================================
__global__ void rmsnorm_kernel(const float* __restrict__ x,
                               const float* __restrict__ w,
                               float* __restrict__ out)
{
    const int row = blockIdx.x;
    const float* xr = x + (size_t)row * DMODEL;
    float s = 0.f;
    for (int i = threadIdx.x; i < DMODEL; i += 256) { float v = xr[i]; s += v * v; }
    #pragma unroll
    for (int off = 16; off; off >>= 1) s += __shfl_down_sync(0xffffffffu, s, off);
    __shared__ float red[8];
    const int warp = threadIdx.x >> 5, lane = threadIdx.x & 31;
    if (lane == 0) red[warp] = s;
    __syncthreads();
    if (warp == 0) {
        float t = (lane < 8) ? red[lane] : 0.f;
        #pragma unroll
        for (int off = 4; off; off >>= 1) t += __shfl_down_sync(0xffu, t, off);
        if (lane == 0) red[0] = t;
    }
    __syncthreads();
    const float inv = rsqrtf(red[0] * (1.0f / DMODEL) + 1e-5f);
    for (int i = threadIdx.x; i < DMODEL; i += 256)
        out[(size_t)row * DMODEL + i] = xr[i] * inv * w[i];
}

// ======================= RoPE ================================================
__global__ void rope_kernel(float* __restrict__ q, float* __restrict__ k,
                            const int* __restrict__ tok_id)
{
    const int idx = blockIdx.x * blockDim.x + threadIdx.x;
    if (idx >= SLEN * NH * 32) return;
    const int i = idx & 31;
    const int h = (idx >> 5) & 15;
    const int s = idx >> 9;
    const double inv = pow(10000.0, -(double)i / 32.0);
    const double ang = (double)tok_id[s] * inv;
    double sd, cd;
    sincos(ang, &sd, &cd);
    const float c = (float)cd, sn = (float)sd;
    const size_t base = (size_t)s * DMODEL + h * HDIM;
    float x1 = q[base + i], x2 = q[base + 32 + i];
    q[base + i]      = x1 * c - x2 * sn;
    q[base + 32 + i] = x1 * sn + x2 * c;
    float y1 = k[base + i], y2 = k[base + 32 + i];
    k[base + i]      = y1 * c - y2 * sn;
    k[base + 32 + i] = y1 * sn + y2 * c;
}

// ======================= local masked attention ==============================
__global__ void attn_kernel(const float* __restrict__ q,
                            const float* __restrict__ k,
                            const float* __restrict__ v,
                            const int* __restrict__ doc_id,
                            const int* __restrict__ tok_id,
                            float* __restrict__ o)
{
    const int s = blockIdx.x;
    const int h = blockIdx.y;
    const int tid = threadIdx.x;
    const int warp = tid >> 5, lane = tid & 31;

    __shared__ float qs[HDIM];
    __shared__ float sc[256];
    __shared__ float red[4];
    __shared__ float oacc[HDIM];

    if (tid < HDIM) qs[tid] = q[(size_t)s * DMODEL + h * HDIM + tid];
    __syncthreads();

    int kstart = s - 127; if (kstart < 0) kstart = 0;
    int kend   = s + 127; if (kend > SLEN - 1) kend = SLEN - 1;
    const int nk = kend - kstart + 1;
    const int myDoc = doc_id[s];
    const int myTok = tok_id[s];

    for (int j = warp; j < nk; j += 4) {
        const int kk = kstart + j;
        const size_t kb = (size_t)kk * DMODEL + h * HDIM;
        float p = qs[lane] * k[kb + lane] + qs[lane + 32] * k[kb + lane + 32];
        #pragma unroll
        for (int off = 16; off; off >>= 1) p += __shfl_down_sync(0xffffffffu, p, off);
        if (lane == 0) {
            const bool ok = (doc_id[kk] == myDoc) && (abs(tok_id[kk] - myTok) < 128);
            sc[j] = ok ? p * 0.125f : -1e30f;
        }
    }
    __syncthreads();

    float m = -1e30f;
    for (int j = tid; j < nk; j += 128) m = fmaxf(m, sc[j]);
    #pragma unroll
    for (int off = 16; off; off >>= 1) m = fmaxf(m, __shfl_down_sync(0xffffffffu, m, off));
    if (lane == 0) red[warp] = m;
    __syncthreads();
    m = fmaxf(fmaxf(red[0], red[1]), fmaxf(red[2], red[3]));
    __syncthreads();

    float sum = 0.f;
    for (int j = tid; j < nk; j += 128) {
        const float e = expf(sc[j] - m);
        sc[j] = e;
        sum += e;
    }
    #pragma unroll
    for (int off = 16; off; off >>= 1) sum += __shfl_down_sync(0xffffffffu, sum, off);
    if (lane == 0) red[warp] = sum;
    __syncthreads();
    sum = red[0] + red[1] + red[2] + red[3];
    const float inv = 1.0f / sum;
    __syncthreads();

    const int d = tid & 63;
    const int half = tid >> 6;
    float acc = 0.f;
    for (int j = half; j < nk; j += 2)
        acc += sc[j] * v[(size_t)(kstart + j) * DMODEL + h * HDIM + d];
    if (half == 1) oacc[d] = acc;
    __syncthreads();
    if (half == 0)
        o[(size_t)s * DMODEL + h * HDIM + d] = (acc + oacc[d]) * inv;
}

// ======================= SiLU gate ===========================================
__global__ void silu_kernel(float* __restrict__ f1, const float* __restrict__ f3)
{
    const int idx = blockIdx.x * blockDim.x + threadIdx.x;
    const float a = f1[idx];
    f1[idx] = (a / (1.0f + expf(-a))) * f3[idx];
}

// ======================= launch ==============================================
static void run_gemm(const __nv_bfloat16* ahi, const __nv_bfloat16* alo,
                     const __nv_bfloat16* whi, const __nv_bfloat16* wlo,
                     const float* bias, const float* res, float* C,
                     int M, int N, int K)
{
    dim3 g(N / 128, M / 128);
    hgemm_kernel<<<g, 256, HG_SMEM>>>(ahi, alo, whi, wlo, bias, res, C, M, N, K);
}

extern "C" void kernel_launch(void* const* d_in, const int* in_sizes, int n_in,
                              void* d_out, int out_size)
{
    const float* x           = (const float*)d_in[0];
    const float* emb_w       = (const float*)d_in[1];
    const float* emb_b       = (const float*)d_in[2];
    const float* wq          = (const float*)d_in[3];
    const float* wk          = (const float*)d_in[4];
    const float* wv          = (const float*)d_in[5];
    const float* wo          = (const float*)d_in[6];
    const float* attn_norm_w = (const float*)d_in[7];
    const float* ffn_norm_w  = (const float*)d_in[8];
    const float* w1          = (const float*)d_in[9];
    const float* w2          = (const float*)d_in[10];
    const float* w3          = (const float*)d_in[11];
    const float* out_norm_w  = (const float*)d_in[12];
    const float* out_w       = (const float*)d_in[13];
    const int*   doc_id      = (const int*)d_in[14];
    const int*   tok_id      = (const int*)d_in[15];
    float* out = (float*)d_out;

    cudaFuncSetAttribute(hgemm_kernel,
                         cudaFuncAttributeMaxDynamicSharedMemorySize, HG_SMEM);

    float *h, *hn, *q, *k, *v, *o, *f1, *f3;
    __nv_bfloat16 *whiP, *wloP, *ahi, *alo;
    cudaGetSymbolAddress((void**)&h,   g_h);
    cudaGetSymbolAddress((void**)&hn,  g_hn);
    cudaGetSymbolAddress((void**)&q,   g_q);
    cudaGetSymbolAddress((void**)&k,   g_k);
    cudaGetSymbolAddress((void**)&v,   g_v);
    cudaGetSymbolAddress((void**)&o,   g_o);
    cudaGetSymbolAddress((void**)&f1,  g_f1);
    cudaGetSymbolAddress((void**)&f3,  g_f3);
    cudaGetSymbolAddress((void**)&whiP, g_whi);
    cudaGetSymbolAddress((void**)&wloP, g_wlo);
    cudaGetSymbolAddress((void**)&ahi, g_ahi);
    cudaGetSymbolAddress((void**)&alo, g_alo);

    const size_t OFF_EMB = 0;
    const size_t OFF_L   = 65536;
    const size_t LSTR    = 16 * (size_t)MEG;
    const size_t OFF_OUT = OFF_L + 4 * LSTR;

    // ---- weight transpose + hi/lo split ----
    {
        dim3 t(32, 8);
        wconv_kernel<<<dim3(DMODEL / 32, IND / 32), t>>>(emb_w, whiP + OFF_EMB,
                                                         wloP + OFF_EMB, IND, DMODEL);
        for (int l = 0; l < NLAYER; l++) {
            const size_t lb = OFF_L + l * LSTR;
            const size_t wqo = (size_t)l * DMODEL * DMODEL;
            const size_t wfo = (size_t)l * DMODEL * FFND;
            wconv_kernel<<<dim3(32, 32), t>>>(wq + wqo, whiP + lb + 0 * MEG,
                                              wloP + lb + 0 * MEG, DMODEL, DMODEL);
            wconv_kernel<<<dim3(32, 32), t>>>(wk + wqo, whiP + lb + 1 * MEG,
                                              wloP + lb + 1 * MEG, DMODEL, DMODEL);
            wconv_kernel<<<dim3(32, 32), t>>>(wv + wqo, whiP + lb + 2 * MEG,
                                              wloP + lb + 2 * MEG, DMODEL, DMODEL);
            wconv_kernel<<<dim3(32, 32), t>>>(wo + wqo, whiP + lb + 3 * MEG,
                                              wloP + lb + 3 * MEG, DMODEL, DMODEL);
            wconv_kernel<<<dim3(128, 32), t>>>(w1 + wfo, whiP + lb + 4 * MEG,
                                               wloP + lb + 4 * MEG, DMODEL, FFND);
            wconv_kernel<<<dim3(128, 32), t>>>(w3 + wfo, whiP + lb + 8 * MEG,
                                               wloP + lb + 8 * MEG, DMODEL, FFND);
            wconv_kernel<<<dim3(32, 128), t>>>(w2 + wfo, whiP + lb + 12 * MEG,
                                               wloP + lb + 12 * MEG, FFND, DMODEL);
        }
        wconv_kernel<<<dim3(OUTD / 32, 32), t>>>(out_w, whiP + OFF_OUT,
                                                 wloP + OFF_OUT, DMODEL, OUTD);
    }

    // ---- embedding: h = x @ emb_w + emb_b ----
    aconv_kernel<<<(SLEN * IND / 4 + 255) / 256, 256>>>(x, ahi, alo, SLEN * IND / 4);
    run_gemm(ahi, alo, whiP + OFF_EMB, wloP + OFF_EMB, emb_b, nullptr, h,
             SLEN, DMODEL, IND);

    for (int l = 0; l < NLAYER; l++) {
        const size_t lb = OFF_L + l * LSTR;

        rmsnorm_kernel<<<SLEN, 256>>>(h, attn_norm_w + (size_t)l * DMODEL, hn);
        aconv_kernel<<<SLEN * DMODEL / 4 / 256, 256>>>(hn, ahi, alo, SLEN * DMODEL / 4);
        run_gemm(ahi, alo, whiP + lb + 0 * MEG, wloP + lb + 0 * MEG, nullptr, nullptr,
                 q, SLEN, DMODEL, DMODEL);
        run_gemm(ahi, alo, whiP + lb + 1 * MEG, wloP + lb + 1 * MEG, nullptr, nullptr,
                 k, SLEN, DMODEL, DMODEL);
        run_gemm(ahi, alo, whiP + lb + 2 * MEG, wloP + lb + 2 * MEG, nullptr, nullptr,
                 v, SLEN, DMODEL, DMODEL);

        rope_kernel<<<(SLEN * NH * 32 + 255) / 256, 256>>>(q, k, tok_id);
        attn_kernel<<<dim3(SLEN, NH), 128>>>(q, k, v, doc_id, tok_id, o);

        aconv_kernel<<<SLEN * DMODEL / 4 / 256, 256>>>(o, ahi, alo, SLEN * DMODEL / 4);
        run_gemm(ahi, alo, whiP + lb + 3 * MEG, wloP + lb + 3 * MEG, nullptr, h,
                 h, SLEN, DMODEL, DMODEL);

        rmsnorm_kernel<<<SLEN, 256>>>(h, ffn_norm_w + (size_t)l * DMODEL, hn);
        aconv_kernel<<<SLEN * DMODEL / 4 / 256, 256>>>(hn, ahi, alo, SLEN * DMODEL / 4);
        run_gemm(ahi, alo, whiP + lb + 4 * MEG, wloP + lb + 4 * MEG, nullptr, nullptr,
                 f1, SLEN, FFND, DMODEL);
        run_gemm(ahi, alo, whiP + lb + 8 * MEG, wloP + lb + 8 * MEG, nullptr, nullptr,
                 f3, SLEN, FFND, DMODEL);

        silu_kernel<<<(SLEN * FFND) / 256, 256>>>(f1, f3);

        aconv_kernel<<<SLEN * FFND / 4 / 256, 256>>>(f1, ahi, alo, SLEN * FFND / 4);
        run_gemm(ahi, alo, whiP + lb + 12 * MEG, wloP + lb + 12 * MEG, nullptr, h,
                 h, SLEN, DMODEL, FFND);
    }

    rmsnorm_kernel<<<SLEN, 256>>>(h, out_norm_w, hn);
    aconv_kernel<<<SLEN * DMODEL / 4 / 256, 256>>>(hn, ahi, alo, SLEN * DMODEL / 4);
    run_gemm(ahi, alo, whiP + OFF_OUT, wloP + OFF_OUT, nullptr, nullptr, out,
             SLEN, OUTD, DMODEL);
}